// round 11
// baseline (speedup 1.0000x reference)
#include <cuda_runtime.h>

#define BB 1024
#define TT 200

// Precomputed x-dependent halves:
// g_Xg[m][j] = b_gate[j] + sum_k X[m][k]*W_gate[k][j]   (j in [0,256))
// g_Xc[m][j] = b_cand[j] + sum_k X[m][k]*W_cand[k][j]   (j in [0,128))
__device__ float g_Xg[(size_t)BB * TT * 256];
__device__ float g_Xc[(size_t)BB * TT * 128];

typedef unsigned long long u64;

__device__ __forceinline__ u64 pack2(float a, float b) {
    u64 r; asm("mov.b64 %0,{%1,%2};" : "=l"(r) : "f"(a), "f"(b)); return r;
}
__device__ __forceinline__ u64 splat2(float a) { return pack2(a, a); }
__device__ __forceinline__ void fma2(u64& d, u64 a, u64 b) {
    asm("fma.rn.f32x2 %0,%1,%2,%0;" : "+l"(d) : "l"(a), "l"(b));
}
__device__ __forceinline__ float2 unpack2(u64 v) {
    float2 r; asm("mov.b64 {%0,%1},%2;" : "=f"(r.x), "=f"(r.y) : "l"(v)); return r;
}

__device__ __forceinline__ float sigmoid_f(float x) {
    return __fdividef(1.0f, 1.0f + __expf(-x));
}
__device__ __forceinline__ float tanh_f(float x) {
    return 1.0f - __fdividef(2.0f, __expf(2.0f * x) + 1.0f);
}

// ---------------------------------------------------------------------------
// Kernel A: Xg/Xc precompute GEMM with packed f32x2 FMA.
// Now reg-capped via __launch_bounds__(256,2) so TWO CTAs fit per SM
// (2 x 99KB smem < 228KB) -> 2 warps/SMSP of latency hiding.
// ---------------------------------------------------------------------------
__global__ __launch_bounds__(256, 2)
void precompute_kernel(const float* __restrict__ X,
                       const float* __restrict__ Wg,
                       const float* __restrict__ bg,
                       const float* __restrict__ Wc,
                       const float* __restrict__ bc)
{
    extern __shared__ float sm[];
    float* Xs = sm;              // [64][132] row-major, padded
    float* Ws = sm + 64 * 132;   // [128][128]

    const int tid = threadIdx.x;
    const int m0  = blockIdx.x * 64;

    #pragma unroll
    for (int i = 0; i < 8; i++) {
        int idx = tid + i * 256;
        int m   = idx >> 5;
        int k4  = idx & 31;
        float4 v = *(const float4*)&X[(size_t)(m0 + m) * 128 + k4 * 4];
        *(float4*)&Xs[m * 132 + k4 * 4] = v;
    }

    const int colg = tid & 31;
    const int rowg = tid >> 5;
    const int c0 = colg * 4;
    const int r0 = rowg * 8;

    for (int nt = 0; nt < 3; nt++) {
        __syncthreads();
        const float* Wsrc; int ldw, n0;
        if (nt < 2) { Wsrc = Wg; ldw = 256; n0 = nt * 128; }
        else        { Wsrc = Wc; ldw = 128; n0 = 0; }
        #pragma unroll
        for (int i = 0; i < 16; i++) {
            int idx = tid + i * 256;
            int k   = idx >> 5;
            int j4  = idx & 31;
            *(float4*)&Ws[k * 128 + j4 * 4] =
                *(const float4*)&Wsrc[(size_t)k * ldw + n0 + j4 * 4];
        }
        __syncthreads();

        u64 acc[8][2];
        #pragma unroll
        for (int r = 0; r < 8; r++) { acc[r][0] = 0ULL; acc[r][1] = 0ULL; }

        for (int k4 = 0; k4 < 32; k4++) {
            float4 xv[8];
            #pragma unroll
            for (int r = 0; r < 8; r++)
                xv[r] = *(const float4*)&Xs[(r0 + r) * 132 + k4 * 4];
            #pragma unroll
            for (int kk = 0; kk < 4; kk++) {
                ulonglong2 wv = *(const ulonglong2*)&Ws[(k4 * 4 + kk) * 128 + c0];
                #pragma unroll
                for (int r = 0; r < 8; r++) {
                    float xs = (kk == 0) ? xv[r].x : (kk == 1) ? xv[r].y
                             : (kk == 2) ? xv[r].z : xv[r].w;
                    u64 xp = splat2(xs);
                    fma2(acc[r][0], xp, wv.x);
                    fma2(acc[r][1], xp, wv.y);
                }
            }
        }

        if (nt < 2) {
            float4 bv = *(const float4*)&bg[n0 + c0];
            #pragma unroll
            for (int r = 0; r < 8; r++) {
                float2 a0 = unpack2(acc[r][0]), a1 = unpack2(acc[r][1]);
                float4 o = make_float4(a0.x + bv.x, a0.y + bv.y,
                                       a1.x + bv.z, a1.y + bv.w);
                *(float4*)&g_Xg[(size_t)(m0 + r0 + r) * 256 + n0 + c0] = o;
            }
        } else {
            float4 bv = *(const float4*)&bc[c0];
            #pragma unroll
            for (int r = 0; r < 8; r++) {
                float2 a0 = unpack2(acc[r][0]), a1 = unpack2(acc[r][1]);
                float4 o = make_float4(a0.x + bv.x, a0.y + bv.y,
                                       a1.x + bv.z, a1.y + bv.w);
                *(float4*)&g_Xc[(size_t)(m0 + r0 + r) * 128 + c0] = o;
            }
        }
    }
}

// ---------------------------------------------------------------------------
// Kernel B: GRU recurrence, crossbar-minimal split. 128 blocks x 128 threads.
// State TRANSPOSED ht/rt/ut[k][8 rows] (stride SPAD=12 floats, 16B aligned):
// the 8 rows at hidden index k arrive as 2 broadcast LDS.128 and feed f32x2
// accumulators (lanes = row pair) with NO packing movs; only weights splat.
// Weight reads have zero redundancy:
//   Phase G: thread owns gate cols (2*tid, 2*tid+1), all 8 rows. Wg: 1 u64/k.
//   Phase C: thread owns cand col tid, all 8 rows.          Wc: 1 f32/k.
// ---------------------------------------------------------------------------
#define SPAD 12

__global__ __launch_bounds__(128, 1)
void gru_kernel(const float* __restrict__ Wg,   // [256][256]
                const float* __restrict__ Wc,   // [256][128]
                const int*   __restrict__ seq_len,
                float* __restrict__ out)        // [1024][200][128]
{
    extern __shared__ float sm[];
    float* Wg_s = sm;                      // [128][256] h-part of W_gate
    float* Wc_s = Wg_s + 128 * 256;        // [128][128] h-part of W_cand
    float* ht   = Wc_s + 128 * 128;        // [128][SPAD] h transposed
    float* rt   = ht   + 128 * SPAD;       // [128][SPAD] r*h transposed
    float* ut   = rt   + 128 * SPAD;       // [128][SPAD] u transposed

    const int tid = threadIdx.x;
    const int b0  = blockIdx.x * 8;

    #pragma unroll
    for (int i = 0; i < 64; i++) {
        int idx = tid + i * 128;
        *(float4*)&Wg_s[idx * 4] = *(const float4*)&Wg[128 * 256 + idx * 4];
    }
    #pragma unroll
    for (int i = 0; i < 32; i++) {
        int idx = tid + i * 128;
        *(float4*)&Wc_s[idx * 4] = *(const float4*)&Wc[128 * 128 + idx * 4];
    }
    for (int i = tid; i < 128 * SPAD; i += 128) ht[i] = 0.0f;
    __syncthreads();

    const int gc = tid * 2;                // gate col pair (0..254)
    int sl[8];
    #pragma unroll
    for (int i = 0; i < 8; i++) sl[i] = seq_len[b0 + i];

    for (int t = 0; t < TT; t++) {
        // ---- Phase G: gates = sigmoid(xg + h @ Wg_h) -----------------------
        float2 xgv[8];
        #pragma unroll
        for (int i = 0; i < 8; i++)
            xgv[i] = *(const float2*)&g_Xg[((size_t)(b0 + i) * TT + t) * 256 + gc];

        // acc[p][c]: rows (2p, 2p+1) packed, col gc+c.
        u64 acc[4][2];
        #pragma unroll
        for (int p = 0; p < 4; p++) {
            acc[p][0] = pack2(xgv[2 * p].x, xgv[2 * p + 1].x);
            acc[p][1] = pack2(xgv[2 * p].y, xgv[2 * p + 1].y);
        }

        #pragma unroll 4
        for (int k = 0; k < 128; k++) {
            ulonglong2 hA = *(const ulonglong2*)&ht[k * SPAD];      // rows 0-3
            ulonglong2 hB = *(const ulonglong2*)&ht[k * SPAD + 4];  // rows 4-7
            float2 wf = unpack2(*(const u64*)&Wg_s[k * 256 + gc]);
            u64 w0 = splat2(wf.x), w1 = splat2(wf.y);
            fma2(acc[0][0], hA.x, w0); fma2(acc[0][1], hA.x, w1);
            fma2(acc[1][0], hA.y, w0); fma2(acc[1][1], hA.y, w1);
            fma2(acc[2][0], hB.x, w0); fma2(acc[2][1], hB.x, w1);
            fma2(acc[3][0], hB.y, w0); fma2(acc[3][1], hB.y, w1);
        }

        float g[8][2];
        #pragma unroll
        for (int p = 0; p < 4; p++) {
            float2 a0 = unpack2(acc[p][0]), a1 = unpack2(acc[p][1]);
            g[2 * p][0]     = sigmoid_f(a0.x);
            g[2 * p + 1][0] = sigmoid_f(a0.y);
            g[2 * p][1]     = sigmoid_f(a1.x);
            g[2 * p + 1][1] = sigmoid_f(a1.y);
        }

        if (tid < 64) {
            // r-gates: cols gc, gc+1 < 128. rt[col][r] = g[r][c] * ht[col][r].
            #pragma unroll
            for (int c = 0; c < 2; c++) {
                const int col = gc + c;
                float4 h0 = *(const float4*)&ht[col * SPAD];
                float4 h1 = *(const float4*)&ht[col * SPAD + 4];
                *(float4*)&rt[col * SPAD] =
                    make_float4(g[0][c] * h0.x, g[1][c] * h0.y,
                                g[2][c] * h0.z, g[3][c] * h0.w);
                *(float4*)&rt[col * SPAD + 4] =
                    make_float4(g[4][c] * h1.x, g[5][c] * h1.y,
                                g[6][c] * h1.z, g[7][c] * h1.w);
            }
        } else {
            // u-gates: cols gc-128, gc-127.
            #pragma unroll
            for (int c = 0; c < 2; c++) {
                const int col = gc + c - 128;
                *(float4*)&ut[col * SPAD] =
                    make_float4(g[0][c], g[1][c], g[2][c], g[3][c]);
                *(float4*)&ut[col * SPAD + 4] =
                    make_float4(g[4][c], g[5][c], g[6][c], g[7][c]);
            }
        }
        __syncthreads();

        // ---- Phase C: cand col tid, all 8 rows -----------------------------
        float xcv[8];
        #pragma unroll
        for (int i = 0; i < 8; i++)
            xcv[i] = g_Xc[((size_t)(b0 + i) * TT + t) * 128 + tid];

        u64 ac[4];
        ac[0] = pack2(xcv[0], xcv[1]); ac[1] = pack2(xcv[2], xcv[3]);
        ac[2] = pack2(xcv[4], xcv[5]); ac[3] = pack2(xcv[6], xcv[7]);

        #pragma unroll 4
        for (int k = 0; k < 128; k++) {
            ulonglong2 pA = *(const ulonglong2*)&rt[k * SPAD];
            ulonglong2 pB = *(const ulonglong2*)&rt[k * SPAD + 4];
            u64 w = splat2(Wc_s[k * 128 + tid]);
            fma2(ac[0], pA.x, w); fma2(ac[1], pA.y, w);
            fma2(ac[2], pB.x, w); fma2(ac[3], pB.y, w);
        }

        float cv[8];
        {
            float2 q;
            q = unpack2(ac[0]); cv[0] = tanh_f(q.x); cv[1] = tanh_f(q.y);
            q = unpack2(ac[1]); cv[2] = tanh_f(q.x); cv[3] = tanh_f(q.y);
            q = unpack2(ac[2]); cv[4] = tanh_f(q.x); cv[5] = tanh_f(q.y);
            q = unpack2(ac[3]); cv[6] = tanh_f(q.x); cv[7] = tanh_f(q.y);
        }

        float4 u0 = *(const float4*)&ut[tid * SPAD];
        float4 u1 = *(const float4*)&ut[tid * SPAD + 4];
        float4 h0 = *(const float4*)&ht[tid * SPAD];
        float4 h1 = *(const float4*)&ht[tid * SPAD + 4];
        float uu[8] = {u0.x, u0.y, u0.z, u0.w, u1.x, u1.y, u1.z, u1.w};
        float hh[8] = {h0.x, h0.y, h0.z, h0.w, h1.x, h1.y, h1.z, h1.w};
        float hn[8];
        #pragma unroll
        for (int i = 0; i < 8; i++) {
            float hw = uu[i] * hh[i] + (1.0f - uu[i]) * cv[i];
            bool v = (t < sl[i]);
            hn[i] = v ? hw : hh[i];
            out[((size_t)(b0 + i) * TT + t) * 128 + tid] = v ? hw : 0.0f;
        }
        *(float4*)&ht[tid * SPAD]     = make_float4(hn[0], hn[1], hn[2], hn[3]);
        *(float4*)&ht[tid * SPAD + 4] = make_float4(hn[4], hn[5], hn[6], hn[7]);
        __syncthreads();
    }
}

// ---------------------------------------------------------------------------
extern "C" void kernel_launch(void* const* d_in, const int* in_sizes, int n_in,
                              void* d_out, int out_size)
{
    (void)in_sizes; (void)n_in; (void)out_size;
    const float* X   = (const float*)d_in[0];   // item_his_eb [1024,200,128]
    const int*   sq  = (const int*)  d_in[1];   // seq_len [1024]
    const float* Wg  = (const float*)d_in[2];   // W_gate [256,256]
    const float* bg  = (const float*)d_in[3];   // b_gate [256]
    const float* Wc  = (const float*)d_in[4];   // W_cand [256,128]
    const float* bc  = (const float*)d_in[5];   // b_cand [128]
    float* out = (float*)d_out;                 // [1024,200,128]

    const int smemA = (64 * 132 + 128 * 128) * 4;                     // 99328
    const int smemB = (128 * 256 + 128 * 128 + 3 * 128 * SPAD) * 4;   // 215040
    cudaFuncSetAttribute(precompute_kernel,
                         cudaFuncAttributeMaxDynamicSharedMemorySize, smemA);
    cudaFuncSetAttribute(gru_kernel,
                         cudaFuncAttributeMaxDynamicSharedMemorySize, smemB);

    precompute_kernel<<<3200, 256, smemA>>>(X, Wg, bg, Wc, bc);
    gru_kernel<<<128, 128, smemB>>>(Wg, Wc, sq, out);
}

// round 13
// speedup vs baseline: 1.3428x; 1.3428x over previous
#include <cuda_runtime.h>

#define BB 1024
#define TT 200

// Precomputed x-dependent halves:
// g_Xg[m][j] = b_gate[j] + sum_k X[m][k]*W_gate[k][j]   (j in [0,256))
// g_Xc[m][j] = b_cand[j] + sum_k X[m][k]*W_cand[k][j]   (j in [0,128))
__device__ float g_Xg[(size_t)BB * TT * 256];
__device__ float g_Xc[(size_t)BB * TT * 128];

typedef unsigned long long u64;

__device__ __forceinline__ u64 pack2(float a, float b) {
    u64 r; asm("mov.b64 %0,{%1,%2};" : "=l"(r) : "f"(a), "f"(b)); return r;
}
__device__ __forceinline__ u64 splat2(float a) { return pack2(a, a); }
__device__ __forceinline__ void fma2(u64& d, u64 a, u64 b) {
    asm("fma.rn.f32x2 %0,%1,%2,%0;" : "+l"(d) : "l"(a), "l"(b));
}
__device__ __forceinline__ float2 unpack2(u64 v) {
    float2 r; asm("mov.b64 {%0,%1},%2;" : "=f"(r.x), "=f"(r.y) : "l"(v)); return r;
}

__device__ __forceinline__ float sigmoid_f(float x) {
    return __fdividef(1.0f, 1.0f + __expf(-x));
}
__device__ __forceinline__ float tanh_f(float x) {
    return 1.0f - __fdividef(2.0f, __expf(2.0f * x) + 1.0f);
}

// ---------------------------------------------------------------------------
// Kernel A: Xg/Xc precompute GEMM with packed f32x2 FMA. R4 body, but now
// __launch_bounds__(256,2): 2 CTAs/SM (2x99KB smem fits) = 4 warps/SMSP for
// latency hiding on this latency-bound kernel. Reg cap 128 (live set ~90).
// ---------------------------------------------------------------------------
__global__ __launch_bounds__(256, 2)
void precompute_kernel(const float* __restrict__ X,
                       const float* __restrict__ Wg,
                       const float* __restrict__ bg,
                       const float* __restrict__ Wc,
                       const float* __restrict__ bc)
{
    extern __shared__ float sm[];
    float* Xs = sm;              // [64][132] row-major, padded
    float* Ws = sm + 64 * 132;   // [128][128]

    const int tid = threadIdx.x;
    const int m0  = blockIdx.x * 64;

    #pragma unroll
    for (int i = 0; i < 8; i++) {
        int idx = tid + i * 256;
        int m   = idx >> 5;
        int k4  = idx & 31;
        float4 v = *(const float4*)&X[(size_t)(m0 + m) * 128 + k4 * 4];
        *(float4*)&Xs[m * 132 + k4 * 4] = v;
    }

    const int colg = tid & 31;
    const int rowg = tid >> 5;
    const int c0 = colg * 4;
    const int r0 = rowg * 8;

    for (int nt = 0; nt < 3; nt++) {
        __syncthreads();
        const float* Wsrc; int ldw, n0;
        if (nt < 2) { Wsrc = Wg; ldw = 256; n0 = nt * 128; }
        else        { Wsrc = Wc; ldw = 128; n0 = 0; }
        #pragma unroll
        for (int i = 0; i < 16; i++) {
            int idx = tid + i * 256;
            int k   = idx >> 5;
            int j4  = idx & 31;
            *(float4*)&Ws[k * 128 + j4 * 4] =
                *(const float4*)&Wsrc[(size_t)k * ldw + n0 + j4 * 4];
        }
        __syncthreads();

        u64 acc[8][2];
        #pragma unroll
        for (int r = 0; r < 8; r++) { acc[r][0] = 0ULL; acc[r][1] = 0ULL; }

        for (int k4 = 0; k4 < 32; k4++) {
            float4 xv[8];
            #pragma unroll
            for (int r = 0; r < 8; r++)
                xv[r] = *(const float4*)&Xs[(r0 + r) * 132 + k4 * 4];
            #pragma unroll
            for (int kk = 0; kk < 4; kk++) {
                ulonglong2 wv = *(const ulonglong2*)&Ws[(k4 * 4 + kk) * 128 + c0];
                #pragma unroll
                for (int r = 0; r < 8; r++) {
                    float xs = (kk == 0) ? xv[r].x : (kk == 1) ? xv[r].y
                             : (kk == 2) ? xv[r].z : xv[r].w;
                    u64 xp = splat2(xs);
                    fma2(acc[r][0], xp, wv.x);
                    fma2(acc[r][1], xp, wv.y);
                }
            }
        }

        if (nt < 2) {
            float4 bv = *(const float4*)&bg[n0 + c0];
            #pragma unroll
            for (int r = 0; r < 8; r++) {
                float2 a0 = unpack2(acc[r][0]), a1 = unpack2(acc[r][1]);
                float4 o = make_float4(a0.x + bv.x, a0.y + bv.y,
                                       a1.x + bv.z, a1.y + bv.w);
                *(float4*)&g_Xg[(size_t)(m0 + r0 + r) * 256 + n0 + c0] = o;
            }
        } else {
            float4 bv = *(const float4*)&bc[c0];
            #pragma unroll
            for (int r = 0; r < 8; r++) {
                float2 a0 = unpack2(acc[r][0]), a1 = unpack2(acc[r][1]);
                float4 o = make_float4(a0.x + bv.x, a0.y + bv.y,
                                       a1.x + bv.z, a1.y + bv.w);
                *(float4*)&g_Xc[(size_t)(m0 + r0 + r) * 128 + c0] = o;
            }
        }
    }
}

// ---------------------------------------------------------------------------
// Kernel B: GRU recurrence — exact R7 (measured best, 725us).
// 128 blocks x 128 threads; row-major state; f32x2 col-pair accumulators;
// h/rh read as float4 per row per 4 k's.
// ---------------------------------------------------------------------------
__global__ __launch_bounds__(128, 1)
void gru_kernel(const float* __restrict__ Wg,   // [256][256]
                const float* __restrict__ Wc,   // [256][128]
                const int*   __restrict__ seq_len,
                float* __restrict__ out)        // [1024][200][128]
{
    extern __shared__ float sm[];
    float* Wg_s = sm;                      // [128][256] (h-part of W_gate)
    float* Wc_s = Wg_s + 128 * 256;        // [128][128] (h-part of W_cand)
    float* h_s  = Wc_s + 128 * 128;        // [8][132]
    float* rh_s = h_s  + 8 * 132;          // [8][132]
    float* u_s  = rh_s + 8 * 132;          // [8][132]

    const int tid = threadIdx.x;
    const int b0  = blockIdx.x * 8;

    #pragma unroll
    for (int i = 0; i < 64; i++) {
        int idx = tid + i * 128;
        *(float4*)&Wg_s[idx * 4] = *(const float4*)&Wg[128 * 256 + idx * 4];
    }
    #pragma unroll
    for (int i = 0; i < 32; i++) {
        int idx = tid + i * 128;
        *(float4*)&Wc_s[idx * 4] = *(const float4*)&Wc[128 * 128 + idx * 4];
    }
    for (int i = tid; i < 8 * 132; i += 128) h_s[i] = 0.0f;
    __syncthreads();

    const int colg = tid & 63;
    const int rowg = tid >> 6;
    const int c0   = colg * 4;             // gate col base
    const int cc0  = colg * 2;             // cand col base
    const int r0   = rowg * 4;             // row base

    int sl[4];
    #pragma unroll
    for (int i = 0; i < 4; i++) sl[i] = seq_len[b0 + r0 + i];

    for (int t = 0; t < TT; t++) {
        // ---- Phase G: gates = sigmoid(xg + h @ Wg_h) -----------------------
        float4 xg[4];
        #pragma unroll
        for (int i = 0; i < 4; i++)
            xg[i] = *(const float4*)&g_Xg[((size_t)(b0 + r0 + i) * TT + t) * 256 + c0];

        u64 acc[4][2];
        #pragma unroll
        for (int i = 0; i < 4; i++) { acc[i][0] = 0ULL; acc[i][1] = 0ULL; }

        #pragma unroll 2
        for (int k4 = 0; k4 < 32; k4++) {
            float4 hv[4];
            #pragma unroll
            for (int i = 0; i < 4; i++)
                hv[i] = *(const float4*)&h_s[(r0 + i) * 132 + k4 * 4];
            #pragma unroll
            for (int kk = 0; kk < 4; kk++) {
                ulonglong2 w2 = *(const ulonglong2*)&Wg_s[(k4 * 4 + kk) * 256 + c0];
                #pragma unroll
                for (int i = 0; i < 4; i++) {
                    float hs = (kk == 0) ? hv[i].x : (kk == 1) ? hv[i].y
                             : (kk == 2) ? hv[i].z : hv[i].w;
                    u64 hp = splat2(hs);
                    fma2(acc[i][0], hp, w2.x);
                    fma2(acc[i][1], hp, w2.y);
                }
            }
        }

        #pragma unroll
        for (int i = 0; i < 4; i++) {
            float2 a0 = unpack2(acc[i][0]), a1 = unpack2(acc[i][1]);
            float4 g;
            g.x = sigmoid_f(a0.x + xg[i].x);
            g.y = sigmoid_f(a0.y + xg[i].y);
            g.z = sigmoid_f(a1.x + xg[i].z);
            g.w = sigmoid_f(a1.y + xg[i].w);
            if (c0 < 128) {
                float4 h4 = *(const float4*)&h_s[(r0 + i) * 132 + c0];
                float4 rh;
                rh.x = g.x * h4.x; rh.y = g.y * h4.y;
                rh.z = g.z * h4.z; rh.w = g.w * h4.w;
                *(float4*)&rh_s[(r0 + i) * 132 + c0] = rh;
            } else {
                *(float4*)&u_s[(r0 + i) * 132 + (c0 - 128)] = g;
            }
        }
        __syncthreads();

        // ---- Phase C: c = tanh(xc + (r*h) @ Wc_h); h update ----------------
        float2 xc[4];
        #pragma unroll
        for (int i = 0; i < 4; i++)
            xc[i] = *(const float2*)&g_Xc[((size_t)(b0 + r0 + i) * TT + t) * 128 + cc0];

        u64 ac[4];
        #pragma unroll
        for (int i = 0; i < 4; i++) ac[i] = 0ULL;

        #pragma unroll 2
        for (int k4 = 0; k4 < 32; k4++) {
            float4 pv[4];
            #pragma unroll
            for (int i = 0; i < 4; i++)
                pv[i] = *(const float4*)&rh_s[(r0 + i) * 132 + k4 * 4];
            #pragma unroll
            for (int kk = 0; kk < 4; kk++) {
                u64 w = *(const u64*)&Wc_s[(k4 * 4 + kk) * 128 + cc0];
                #pragma unroll
                for (int i = 0; i < 4; i++) {
                    float ps = (kk == 0) ? pv[i].x : (kk == 1) ? pv[i].y
                             : (kk == 2) ? pv[i].z : pv[i].w;
                    fma2(ac[i], splat2(ps), w);
                }
            }
        }

        #pragma unroll
        for (int i = 0; i < 4; i++) {
            float2 a = unpack2(ac[i]);
            float cv0 = tanh_f(a.x + xc[i].x);
            float cv1 = tanh_f(a.y + xc[i].y);
            float2 hh = *(const float2*)&h_s[(r0 + i) * 132 + cc0];
            float2 uu = *(const float2*)&u_s[(r0 + i) * 132 + cc0];
            float hn0 = uu.x * hh.x + (1.0f - uu.x) * cv0;
            float hn1 = uu.y * hh.y + (1.0f - uu.y) * cv1;
            bool valid = (t < sl[i]);
            float2 hw, yw;
            hw.x = valid ? hn0 : hh.x;   hw.y = valid ? hn1 : hh.y;
            yw.x = valid ? hn0 : 0.0f;   yw.y = valid ? hn1 : 0.0f;
            *(float2*)&h_s[(r0 + i) * 132 + cc0] = hw;
            *(float2*)&out[((size_t)(b0 + r0 + i) * TT + t) * 128 + cc0] = yw;
        }
        __syncthreads();
    }
}

// ---------------------------------------------------------------------------
extern "C" void kernel_launch(void* const* d_in, const int* in_sizes, int n_in,
                              void* d_out, int out_size)
{
    (void)in_sizes; (void)n_in; (void)out_size;
    const float* X   = (const float*)d_in[0];   // item_his_eb [1024,200,128]
    const int*   sq  = (const int*)  d_in[1];   // seq_len [1024]
    const float* Wg  = (const float*)d_in[2];   // W_gate [256,256]
    const float* bg  = (const float*)d_in[3];   // b_gate [256]
    const float* Wc  = (const float*)d_in[4];   // W_cand [256,128]
    const float* bc  = (const float*)d_in[5];   // b_cand [128]
    float* out = (float*)d_out;                 // [1024,200,128]

    const int smemA = (64 * 132 + 128 * 128) * 4;                     // 99328
    const int smemB = (128 * 256 + 128 * 128 + 3 * 8 * 132) * 4;      // 209280
    cudaFuncSetAttribute(precompute_kernel,
                         cudaFuncAttributeMaxDynamicSharedMemorySize, smemA);
    cudaFuncSetAttribute(gru_kernel,
                         cudaFuncAttributeMaxDynamicSharedMemorySize, smemB);

    precompute_kernel<<<3200, 256, smemA>>>(X, Wg, bg, Wc, bc);
    gru_kernel<<<128, 128, smemB>>>(Wg, Wc, sq, out);
}